// round 2
// baseline (speedup 1.0000x reference)
#include <cuda_runtime.h>
#include <cuda_bf16.h>

#define BATCH 8192
#define TMAX  2048
#define ROWSTRIDE (TMAX + 1)   // 2049 ints per row (last is T)

__global__ __launch_bounds__(256)
void hmm_fwd_kernel(const int* __restrict__ xin,
                    const float* __restrict__ prior_l,
                    const float* __restrict__ trans_l,
                    const float* __restrict__ emis_l,
                    float* __restrict__ out) {
    const int gtid = blockIdx.x * blockDim.x + threadIdx.x;
    const int warp = gtid >> 5;
    const int lane = gtid & 31;
    if (warp >= BATCH) return;

    // ---- constants (softmaxes), recomputed per thread, all cached loads ----
    // priors
    float pe0 = __expf(prior_l[0]), pe1 = __expf(prior_l[1]);
    float pinv = 1.0f / (pe0 + pe1);
    const float p0 = pe0 * pinv, p1 = pe1 * pinv;
    // A = softmax rows of trans_l (A[i][j])
    float t00 = __expf(trans_l[0]), t01 = __expf(trans_l[1]);
    float t10 = __expf(trans_l[2]), t11 = __expf(trans_l[3]);
    float r0 = 1.0f / (t00 + t01), r1 = 1.0f / (t10 + t11);
    const float A00 = t00 * r0, A01 = t01 * r0;
    const float A10 = t10 * r1, A11 = t11 * r1;
    // emission probs: e[s][obs] = softmax(emis_l[s])[obs]
    float e00x = __expf(emis_l[0]), e01x = __expf(emis_l[1]);
    float e10x = __expf(emis_l[2]), e11x = __expf(emis_l[3]);
    float s0 = 1.0f / (e00x + e01x), s1 = 1.0f / (e10x + e11x);
    const float E00 = e00x * s0;  // P(obs=0 | s=0)
    const float E01 = e01x * s0;  // P(obs=1 | s=0)
    const float E10 = e10x * s1;  // P(obs=0 | s=1)
    const float E11 = e11x * s1;  // P(obs=1 | s=1)

    // alpha_t = M_x * alpha_{t-1},  M_x = [[Ex0*A00, Ex0*A10],[Ex1*A01, Ex1*A11]]
    // where Ex0 = P(obs=x|s=0), Ex1 = P(obs=x|s=1)
    const float Ma00 = E00 * A00, Ma01 = E00 * A10, Ma10 = E10 * A01, Ma11 = E10 * A11; // x=0
    const float Mb00 = E01 * A00, Mb01 = E01 * A10, Mb10 = E11 * A01, Mb11 = E11 * A11; // x=1

    const int* __restrict__ row = xin + (size_t)warp * ROWSTRIDE;
    const int T = row[TMAX];      // last column
    const int n = T - 1;          // number of scan steps, uses x[1..T-1]

    // per-lane contiguous chunk of timesteps in [1, T)
    const int c = (n + 31) >> 5;
    int t  = 1 + lane * c;
    int te = t + c;
    if (te > T) te = T;

    // accumulate ordered product of M_{x_t} over the chunk (identity init)
    float p00 = 1.f, p01 = 0.f, p10 = 0.f, p11 = 1.f;
    #pragma unroll 4
    for (; t < te; ++t) {
        const int xt = row[t];
        const float m00 = xt ? Mb00 : Ma00;
        const float m01 = xt ? Mb01 : Ma01;
        const float m10 = xt ? Mb10 : Ma10;
        const float m11 = xt ? Mb11 : Ma11;
        const float q00 = m00 * p00 + m01 * p10;
        const float q01 = m00 * p01 + m01 * p11;
        const float q10 = m10 * p00 + m11 * p10;
        const float q11 = m10 * p01 + m11 * p11;
        p00 = q00; p01 = q01; p10 = q10; p11 = q11;
    }

    // ordered segment reduce across lanes: P_total = P31 * P30 * ... * P0
    // at offset d, lane l absorbs lane l+d on its LEFT:  P_l := P_{l+d} * P_l
    #pragma unroll
    for (int d = 1; d < 32; d <<= 1) {
        const float u00 = __shfl_down_sync(0xFFFFFFFFu, p00, d);
        const float u01 = __shfl_down_sync(0xFFFFFFFFu, p01, d);
        const float u10 = __shfl_down_sync(0xFFFFFFFFu, p10, d);
        const float u11 = __shfl_down_sync(0xFFFFFFFFu, p11, d);
        if (lane + d < 32) {
            const float q00 = u00 * p00 + u01 * p10;
            const float q01 = u00 * p01 + u01 * p11;
            const float q10 = u10 * p00 + u11 * p10;
            const float q11 = u10 * p01 + u11 * p11;
            p00 = q00; p01 = q01; p10 = q10; p11 = q11;
        }
    }

    if (lane == 0) {
        const int x0 = row[0];
        const float a0 = (x0 ? E01 : E00) * p0;   // alpha0[0]
        const float a1 = (x0 ? E11 : E10) * p1;   // alpha0[1]
        const float f0 = p00 * a0 + p01 * a1;
        const float f1 = p10 * a0 + p11 * a1;
        out[warp] = f0 + f1;
    }
}

extern "C" void kernel_launch(void* const* d_in, const int* in_sizes, int n_in,
                              void* d_out, int out_size) {
    const int*   xin     = (const int*)d_in[0];
    const float* prior_l = (const float*)d_in[1];
    const float* trans_l = (const float*)d_in[2];
    const float* emis_l  = (const float*)d_in[3];
    float* out = (float*)d_out;

    const int threads = 256;                 // 8 warps/block
    const int blocks  = (BATCH * 32) / threads;  // 1024 blocks
    hmm_fwd_kernel<<<blocks, threads>>>(xin, prior_l, trans_l, emis_l, out);
}

// round 3
// speedup vs baseline: 1.1031x; 1.1031x over previous
#include <cuda_runtime.h>
#include <cuda_bf16.h>

#define BATCH 8192
#define TMAX  2048
#define ROWSTRIDE (TMAX + 1)   // 2049 ints per row (last is T)

// Layered LUT: entry for a product of v in [0,4] consecutive per-obs matrices,
// index = (2^v - 1) + (bits of the v observations, element 0 = LSB).
// Entry 0 is the identity. 31 entries total.
__global__ __launch_bounds__(256)
void hmm_fwd_kernel(const int* __restrict__ xin,
                    const float* __restrict__ prior_l,
                    const float* __restrict__ trans_l,
                    const float* __restrict__ emis_l,
                    float* __restrict__ out) {
    __shared__ float4 lut[32];

    const int tid  = threadIdx.x;
    const int gtid = blockIdx.x * blockDim.x + tid;
    const int warp = gtid >> 5;
    const int lane = gtid & 31;

    // ---- softmax constants (uniform, L1-cached) ----
    float pe0 = __expf(prior_l[0]), pe1 = __expf(prior_l[1]);
    float pinv = 1.0f / (pe0 + pe1);
    const float p0 = pe0 * pinv, p1 = pe1 * pinv;

    float t00 = __expf(trans_l[0]), t01 = __expf(trans_l[1]);
    float t10 = __expf(trans_l[2]), t11 = __expf(trans_l[3]);
    float r0 = 1.0f / (t00 + t01), r1 = 1.0f / (t10 + t11);
    const float A00 = t00 * r0, A01 = t01 * r0;
    const float A10 = t10 * r1, A11 = t11 * r1;

    float e00x = __expf(emis_l[0]), e01x = __expf(emis_l[1]);
    float e10x = __expf(emis_l[2]), e11x = __expf(emis_l[3]);
    float s0 = 1.0f / (e00x + e01x), s1 = 1.0f / (e10x + e11x);
    const float E00 = e00x * s0, E01 = e01x * s0;
    const float E10 = e10x * s1, E11 = e11x * s1;

    // per-obs transition matrices: alpha' = M_x * alpha
    const float Ma00 = E00 * A00, Ma01 = E00 * A10, Ma10 = E10 * A01, Ma11 = E10 * A11; // x=0
    const float Mb00 = E01 * A00, Mb01 = E01 * A10, Mb10 = E11 * A01, Mb11 = E11 * A11; // x=1

    // ---- build layered LUT (31 entries) ----
    if (tid < 31) {
        int v = 0;
        while ((2 << v) <= tid + 1) ++v;          // v = floor(log2(tid+1))
        int idx = (tid + 1) - (1 << v);
        float c00 = 1.f, c01 = 0.f, c10 = 0.f, c11 = 1.f;
        for (int i = 0; i < v; ++i) {
            int b = (idx >> i) & 1;
            float m00 = b ? Mb00 : Ma00, m01 = b ? Mb01 : Ma01;
            float m10 = b ? Mb10 : Ma10, m11 = b ? Mb11 : Ma11;
            float q00 = m00 * c00 + m01 * c10;
            float q01 = m00 * c01 + m01 * c11;
            float q10 = m10 * c00 + m11 * c10;
            float q11 = m10 * c01 + m11 * c11;
            c00 = q00; c01 = q01; c10 = q10; c11 = q11;
        }
        lut[tid] = make_float4(c00, c01, c10, c11);
    }
    __syncthreads();

    const int* __restrict__ row = xin + (size_t)warp * ROWSTRIDE;
    const int T = row[TMAX];

    // running product (only lane 0's copy is authoritative after the loop)
    float r00 = 1.f, r01 = 0.f, r10 = 0.f, r11 = 1.f;

    // scalar peel until 16B alignment of (row + t)
    const int mis = (int)(((size_t)warp * ROWSTRIDE + 1) & 3);
    const int t0  = 1 + ((4 - mis) & 3);
    const int pe  = t0 < T ? t0 : T;
    for (int t = 1; t < pe; ++t) {                // uniform across warp (<=3 iters)
        int b = row[t];
        float m00 = b ? Mb00 : Ma00, m01 = b ? Mb01 : Ma01;
        float m10 = b ? Mb10 : Ma10, m11 = b ? Mb11 : Ma11;
        float q00 = m00 * r00 + m01 * r10;
        float q01 = m00 * r01 + m01 * r11;
        float q10 = m10 * r00 + m11 * r10;
        float q11 = m10 * r01 + m11 * r11;
        r00 = q00; r01 = q01; r10 = q10; r11 = q11;
    }

    // vectorized main loop: 256 consecutive timesteps per warp-iteration
    for (int s = t0; s < T; s += 256) {
        const int pos = s + 8 * lane;             // this lane's 8 contiguous elems
        int v = T - pos;                          // valid prefix length
        v = v < 0 ? 0 : (v > 8 ? 8 : v);

        int e0 = 0, e1 = 0, e2 = 0, e3 = 0, e4 = 0, e5 = 0, e6 = 0, e7 = 0;
        if (v > 0) {
            if (pos + 8 <= TMAX) {                // fully inside x region, aligned
                const int4* p = (const int4*)(row + pos);
                int4 a = p[0];
                int4 b4 = p[1];
                e0 = a.x;  e1 = a.y;  e2 = a.z;  e3 = a.w;
                e4 = b4.x; e5 = b4.y; e6 = b4.z; e7 = b4.w;
            } else {                              // rare tail near row end
                e0 = row[pos];
                if (v > 1) e1 = row[pos + 1];
                if (v > 2) e2 = row[pos + 2];
                if (v > 3) e3 = row[pos + 3];
                if (v > 4) e4 = row[pos + 4];
                if (v > 5) e5 = row[pos + 5];
                if (v > 6) e6 = row[pos + 6];
                if (v > 7) e7 = row[pos + 7];
            }
        }

        const int idxA = e0 | (e1 << 1) | (e2 << 2) | (e3 << 3);
        const int idxB = e4 | (e5 << 1) | (e6 << 2) | (e7 << 3);
        const int vA = v > 4 ? 4 : v;
        const int vB = v > 4 ? v - 4 : 0;
        const float4 MA = lut[((1 << vA) - 1) + (idxA & ((1 << vA) - 1))];
        const float4 MB = lut[((1 << vB) - 1) + (idxB & ((1 << vB) - 1))];

        // chunk = MB * MA  (elements pos..pos+3 applied first)
        float c00 = MB.x * MA.x + MB.y * MA.z;
        float c01 = MB.x * MA.y + MB.y * MA.w;
        float c10 = MB.z * MA.x + MB.w * MA.z;
        float c11 = MB.z * MA.y + MB.w * MA.w;

        // ordered warp reduce: lane l absorbs lane l+d on its left (later steps)
        #pragma unroll
        for (int d = 1; d < 32; d <<= 1) {
            const float u00 = __shfl_down_sync(0xFFFFFFFFu, c00, d);
            const float u01 = __shfl_down_sync(0xFFFFFFFFu, c01, d);
            const float u10 = __shfl_down_sync(0xFFFFFFFFu, c10, d);
            const float u11 = __shfl_down_sync(0xFFFFFFFFu, c11, d);
            if (lane + d < 32) {
                const float q00 = u00 * c00 + u01 * c10;
                const float q01 = u00 * c01 + u01 * c11;
                const float q10 = u10 * c00 + u11 * c10;
                const float q11 = u10 * c01 + u11 * c11;
                c00 = q00; c01 = q01; c10 = q10; c11 = q11;
            }
        }

        if (lane == 0) {                          // fold 256-step product
            const float q00 = c00 * r00 + c01 * r10;
            const float q01 = c00 * r01 + c01 * r11;
            const float q10 = c10 * r00 + c11 * r10;
            const float q11 = c10 * r01 + c11 * r11;
            r00 = q00; r01 = q01; r10 = q10; r11 = q11;
        }
    }

    if (lane == 0) {
        const int x0 = row[0];
        const float a0 = (x0 ? E01 : E00) * p0;
        const float a1 = (x0 ? E11 : E10) * p1;
        const float f0 = r00 * a0 + r01 * a1;
        const float f1 = r10 * a0 + r11 * a1;
        out[warp] = f0 + f1;
    }
}

extern "C" void kernel_launch(void* const* d_in, const int* in_sizes, int n_in,
                              void* d_out, int out_size) {
    const int*   xin     = (const int*)d_in[0];
    const float* prior_l = (const float*)d_in[1];
    const float* trans_l = (const float*)d_in[2];
    const float* emis_l  = (const float*)d_in[3];
    float* out = (float*)d_out;

    const int threads = 256;                     // 8 warps/block, warp-per-row
    const int blocks  = (BATCH * 32) / threads;  // 1024 blocks
    hmm_fwd_kernel<<<blocks, threads>>>(xin, prior_l, trans_l, emis_l, out);
}

// round 5
// speedup vs baseline: 1.1737x; 1.0640x over previous
#include <cuda_runtime.h>
#include <cuda_bf16.h>

#define BATCH 8192
#define TMAX  2048
#define ROWSTRIDE (TMAX + 1)   // 2049 ints per row (last is T)

// Layered LUT: layer v (v=0..8) holds products of v consecutive per-obs
// matrices; layer base offset = 2^v - 1, entry index = observation bits
// (chronologically first element = LSB). 511 entries total, entry 0 = identity.
// float4 = (c00, c01, c10, c11), alpha' = C * alpha.

__device__ __forceinline__ void load_tile(const int* __restrict__ row, int s, int T,
                                          int lane,
                                          int4& a0, int4& a1, int4& a2, int4& a3) {
    a0 = make_int4(0, 0, 0, 0); a1 = a0; a2 = a0; a3 = a0;
    const int pos = s + (lane << 4);
    if (pos < T) {
        if (pos + 16 <= ROWSTRIDE) {          // stays inside this row's storage
            const int4* p = (const int4*)(row + pos);
            a0 = p[0]; a1 = p[1]; a2 = p[2]; a3 = p[3];
        } else {                               // rare: pos >= 2034, v <= 14
            const int v = T - pos;
            a0.x = row[pos];
            if (v > 1)  a0.y = row[pos + 1];
            if (v > 2)  a0.z = row[pos + 2];
            if (v > 3)  a0.w = row[pos + 3];
            if (v > 4)  a1.x = row[pos + 4];
            if (v > 5)  a1.y = row[pos + 5];
            if (v > 6)  a1.z = row[pos + 6];
            if (v > 7)  a1.w = row[pos + 7];
            if (v > 8)  a2.x = row[pos + 8];
            if (v > 9)  a2.y = row[pos + 9];
            if (v > 10) a2.z = row[pos + 10];
            if (v > 11) a2.w = row[pos + 11];
            if (v > 12) a3.x = row[pos + 12];
            if (v > 13) a3.y = row[pos + 13];
            if (v > 14) a3.z = row[pos + 14];
        }
    }
}

__global__ __launch_bounds__(256)
void hmm_fwd_kernel(const int* __restrict__ xin,
                    const float* __restrict__ prior_l,
                    const float* __restrict__ trans_l,
                    const float* __restrict__ emis_l,
                    float* __restrict__ out) {
    __shared__ float4 lut[511];

    const int tid  = threadIdx.x;
    const int gtid = blockIdx.x * blockDim.x + tid;
    const int warp = gtid >> 5;
    const int lane = gtid & 31;

    // ---- softmax constants (uniform, L1-cached) ----
    float pe0 = __expf(prior_l[0]), pe1 = __expf(prior_l[1]);
    float pinv = 1.0f / (pe0 + pe1);
    const float p0 = pe0 * pinv, p1 = pe1 * pinv;

    float t00 = __expf(trans_l[0]), t01 = __expf(trans_l[1]);
    float t10 = __expf(trans_l[2]), t11 = __expf(trans_l[3]);
    float r0 = 1.0f / (t00 + t01), r1 = 1.0f / (t10 + t11);
    const float A00 = t00 * r0, A01 = t01 * r0;
    const float A10 = t10 * r1, A11 = t11 * r1;

    float e00x = __expf(emis_l[0]), e01x = __expf(emis_l[1]);
    float e10x = __expf(emis_l[2]), e11x = __expf(emis_l[3]);
    float s0 = 1.0f / (e00x + e01x), s1 = 1.0f / (e10x + e11x);
    const float E00 = e00x * s0, E01 = e01x * s0;
    const float E10 = e10x * s1, E11 = e11x * s1;

    // per-obs step matrices: alpha' = M_x * alpha
    const float Ma00 = E00 * A00, Ma01 = E00 * A10, Ma10 = E10 * A01, Ma11 = E10 * A11;
    const float Mb00 = E01 * A00, Mb01 = E01 * A10, Mb10 = E11 * A01, Mb11 = E11 * A11;

    // ---- build layered LUT by doubling ----
    if (tid == 0) lut[0] = make_float4(1.f, 0.f, 0.f, 1.f);
    __syncthreads();
    #pragma unroll
    for (int v = 0; v < 8; ++v) {
        const int cnt = 2 << v;                      // entries in layer v+1
        for (int i = tid; i < cnt; i += 256) {
            const int b = (i >> v) & 1;
            const float4 P = lut[(1 << v) - 1 + (i & ((1 << v) - 1))];
            const float m00 = b ? Mb00 : Ma00, m01 = b ? Mb01 : Ma01;
            const float m10 = b ? Mb10 : Ma10, m11 = b ? Mb11 : Ma11;
            lut[(2 << v) - 1 + i] = make_float4(
                m00 * P.x + m01 * P.z,
                m00 * P.y + m01 * P.w,
                m10 * P.x + m11 * P.z,
                m10 * P.y + m11 * P.w);
        }
        __syncthreads();
    }

    const int* __restrict__ row = xin + (size_t)warp * ROWSTRIDE;
    const int T = row[TMAX];

    // running product; only lane 0's copy is authoritative
    float r00 = 1.f, r01 = 0.f, r10 = 0.f, r11 = 1.f;

    // scalar peel to 16B alignment of (row + t):  row base ≡ warp mod 4 (2049 ≡ 1)
    const int mis = (warp + 1) & 3;
    const int t0  = 1 + ((4 - mis) & 3);
    const int pe  = t0 < T ? t0 : T;
    for (int t = 1; t < pe; ++t) {
        const int b = row[t];
        const float m00 = b ? Mb00 : Ma00, m01 = b ? Mb01 : Ma01;
        const float m10 = b ? Mb10 : Ma10, m11 = b ? Mb11 : Ma11;
        const float q00 = m00 * r00 + m01 * r10;
        const float q01 = m00 * r01 + m01 * r11;
        const float q10 = m10 * r00 + m11 * r10;
        const float q11 = m10 * r01 + m11 * r11;
        r00 = q00; r01 = q01; r10 = q10; r11 = q11;
    }

    // main loop: 512 consecutive timesteps per warp-iteration, software-pipelined
    int4 a0, a1, a2, a3;
    load_tile(row, t0, T, lane, a0, a1, a2, a3);

    for (int s = t0; s < T; s += 512) {
        // prefetch next tile while we crunch this one
        int4 n0 = make_int4(0,0,0,0), n1 = n0, n2 = n0, n3 = n0;
        if (s + 512 < T) load_tile(row, s + 512, T, lane, n0, n1, n2, n3);

        const int pos = s + (lane << 4);

        // pack observation bits (arithmetic; garbage is killed by layer mask)
        const int nA0 = a0.x + 2 * a0.y + 4 * a0.z + 8 * a0.w;
        const int nA1 = a1.x + 2 * a1.y + 4 * a1.z + 8 * a1.w;
        const int nB0 = a2.x + 2 * a2.y + 4 * a2.z + 8 * a2.w;
        const int nB1 = a3.x + 2 * a3.y + 4 * a3.z + 8 * a3.w;
        const int idxA = nA0 + 16 * nA1;
        const int idxB = nB0 + 16 * nB1;

        int rem = T - pos;
        rem = rem < 0 ? 0 : (rem > 16 ? 16 : rem);
        const int vA = rem < 8 ? rem : 8;
        const int vB = rem - vA;

        const float4 MA = lut[((1 << vA) - 1) + (idxA & ((1 << vA) - 1))];
        const float4 MB = lut[((1 << vB) - 1) + (idxB & ((1 << vB) - 1))];

        // 16-step chunk product: C = MB * MA
        float c00 = MB.x * MA.x + MB.y * MA.z;
        float c01 = MB.x * MA.y + MB.y * MA.w;
        float c10 = MB.z * MA.x + MB.w * MA.z;
        float c11 = MB.z * MA.y + MB.w * MA.w;

        // ordered warp reduce (lane l absorbs lane l+d, which is later in time)
        #pragma unroll
        for (int d = 1; d < 32; d <<= 1) {
            const float u00 = __shfl_down_sync(0xFFFFFFFFu, c00, d);
            const float u01 = __shfl_down_sync(0xFFFFFFFFu, c01, d);
            const float u10 = __shfl_down_sync(0xFFFFFFFFu, c10, d);
            const float u11 = __shfl_down_sync(0xFFFFFFFFu, c11, d);
            if (lane + d < 32) {
                const float q00 = u00 * c00 + u01 * c10;
                const float q01 = u00 * c01 + u01 * c11;
                const float q10 = u10 * c00 + u11 * c10;
                const float q11 = u10 * c01 + u11 * c11;
                c00 = q00; c01 = q01; c10 = q10; c11 = q11;
            }
        }

        // fold (valid on lane 0 only, computed everywhere to skip the predicate)
        {
            const float q00 = c00 * r00 + c01 * r10;
            const float q01 = c00 * r01 + c01 * r11;
            const float q10 = c10 * r00 + c11 * r10;
            const float q11 = c10 * r01 + c11 * r11;
            r00 = q00; r01 = q01; r10 = q10; r11 = q11;
        }

        a0 = n0; a1 = n1; a2 = n2; a3 = n3;
    }

    if (lane == 0) {
        const int x0 = row[0];
        const float al0 = (x0 ? E01 : E00) * p0;
        const float al1 = (x0 ? E11 : E10) * p1;
        out[warp] = (r00 * al0 + r01 * al1) + (r10 * al0 + r11 * al1);
    }
}

extern "C" void kernel_launch(void* const* d_in, const int* in_sizes, int n_in,
                              void* d_out, int out_size) {
    const int*   xin     = (const int*)d_in[0];
    const float* prior_l = (const float*)d_in[1];
    const float* trans_l = (const float*)d_in[2];
    const float* emis_l  = (const float*)d_in[3];
    float* out = (float*)d_out;

    const int threads = 256;                     // 8 warps/block, warp-per-row
    const int blocks  = (BATCH * 32) / threads;  // 1024 blocks
    hmm_fwd_kernel<<<blocks, threads>>>(xin, prior_l, trans_l, emis_l, out);
}